// round 4
// baseline (speedup 1.0000x reference)
#include <cuda_runtime.h>
#include <cstdint>
#include <cstddef>

// Problem constants
#define NB   8
#define CIN  64
#define COUT 64
#define HH   128
#define WW   128
#define NCTX 16
// K*K
#define KK9  9

// ---------------------------------------------------------------------------
// Device scratch (no allocations allowed)
// ---------------------------------------------------------------------------
__device__ float g_meanx[NB * CIN];                 // per (b,c) spatial mean of x
__device__ float g_ctxvec[NB * NCTX];               // (B, 16)
__device__ float g_W2[NB * CIN * KK9 * COUT];       // composed kernels, layout [b][c_in][kk][oc]

// ---------------------------------------------------------------------------
// K1: mean over H*W for each (b,c) plane.  512 blocks x 256 threads.
// ---------------------------------------------------------------------------
__global__ void k_mean(const float* __restrict__ x) {
    const int plane = blockIdx.x;                   // b*64 + c
    const float4* xp = (const float4*)(x + (size_t)plane * (HH * WW));
    float s = 0.f;
    for (int i = threadIdx.x; i < (HH * WW) / 4; i += 256) {
        float4 v = xp[i];
        s += (v.x + v.y) + (v.z + v.w);
    }
    __shared__ float red[8];
    #pragma unroll
    for (int o = 16; o; o >>= 1) s += __shfl_down_sync(0xffffffffu, s, o);
    if ((threadIdx.x & 31) == 0) red[threadIdx.x >> 5] = s;
    __syncthreads();
    if (threadIdx.x == 0) {
        float t = 0.f;
        #pragma unroll
        for (int i = 0; i < 8; i++) t += red[i];
        g_meanx[plane] = t * (1.0f / (HH * WW));
    }
}

// ---------------------------------------------------------------------------
// K2: ctx_vec[b,j] = ctx_w[j,:] . meanx[b,:] + ctx_b[j].  1 block x 128 thr.
// ---------------------------------------------------------------------------
__global__ void k_ctx(const float* __restrict__ ctx_w, const float* __restrict__ ctx_b) {
    const int t = threadIdx.x;            // 0..127
    const int b = t >> 4;
    const int j = t & 15;
    float s = ctx_b[j];
    #pragma unroll 16
    for (int c = 0; c < CIN; c++) s += g_meanx[b * CIN + c] * ctx_w[j * CIN + c];
    g_ctxvec[t] = s;
}

// ---------------------------------------------------------------------------
// K3: per (b,o): generate 576-elem kernel row, tanh, mean-center by
// sigmoid(gamma[o]), then compose with value_w:
//   W2[b,o,c',kk] = sum_c (tanh(..)-lam*mean)[c,kk] * value_w[c,c']
// Stored transposed as g_W2[b][c'][kk][o] for the main conv.
// 512 blocks x 576 threads.
// ---------------------------------------------------------------------------
__global__ void k_gen(const float* __restrict__ kg_w, const float* __restrict__ kg_b,
                      const float* __restrict__ gamma, const float* __restrict__ value_w) {
    const int b = blockIdx.x >> 6;
    const int o = blockIdx.x & 63;
    const int t = threadIdx.x;            // 0..575  (t = c*9 + kk)

    __shared__ float Wsh[576];
    __shared__ float red[18];
    __shared__ float smean;

    float cv[NCTX];
    #pragma unroll
    for (int j = 0; j < NCTX; j++) cv[j] = g_ctxvec[b * NCTX + j];

    const int idx = o * 576 + t;          // row into kg_w / kg_b
    const float4* wr = (const float4*)(kg_w + (size_t)idx * NCTX);
    float s = kg_b[idx];
    #pragma unroll
    for (int q = 0; q < 4; q++) {
        float4 w = wr[q];
        s += cv[q * 4 + 0] * w.x + cv[q * 4 + 1] * w.y +
             cv[q * 4 + 2] * w.z + cv[q * 4 + 3] * w.w;
    }
    const float v = tanhf(s);

    // mean over the 576 elements of this (b,o) row
    float r = v;
    #pragma unroll
    for (int off = 16; off; off >>= 1) r += __shfl_down_sync(0xffffffffu, r, off);
    if ((t & 31) == 0) red[t >> 5] = r;
    __syncthreads();
    if (t == 0) {
        float tt = 0.f;
        #pragma unroll
        for (int i = 0; i < 18; i++) tt += red[i];
        smean = tt * (1.0f / 576.0f);
    }
    __syncthreads();

    const float lam = 1.0f / (1.0f + expf(-gamma[o]));
    Wsh[t] = v - lam * smean;
    __syncthreads();

    // compose with value projection: c2 = value input channel
    const int c2 = t / 9;
    const int kk = t - c2 * 9;
    float acc = 0.f;
    #pragma unroll 8
    for (int c = 0; c < CIN; c++)
        acc += Wsh[c * 9 + kk] * value_w[c * CIN + c2];

    g_W2[(((size_t)b * CIN + c2) * KK9 + kk) * COUT + o] = acc;
}

// ---------------------------------------------------------------------------
// K4: main per-sample 3x3 conv on x with composed kernels W2, + bias, ReLU.
// Block: 128 threads; tile 16 rows x 32 cols outputs x 16 output channels.
// Thread: 4 oc x 16 px register tile. Input channels streamed in chunks of 8.
// Grid: (4 tilecols, 8 tilerows, 8 batch * 4 ocgroups) = 1024 blocks.
// ---------------------------------------------------------------------------
__global__ void __launch_bounds__(128) k_conv(const float* __restrict__ x,
                                              const float* __restrict__ bias,
                                              float* __restrict__ out) {
    __shared__ float sin_[8][18][36];     // [cc][row][col], col pad 34->36 (anti-conflict + align)
    __shared__ float sw[8 * KK9 * 16];    // [cc][kk][oc_local]  = 1152 floats

    const int tid = threadIdx.x;
    const int tc  = blockIdx.x;           // 0..3
    const int tr  = blockIdx.y;           // 0..7
    const int b   = blockIdx.z >> 2;
    const int ocg = blockIdx.z & 3;
    const int r0  = tr * 16;
    const int c0  = tc * 32;

    const int og  = tid & 3;              // oc sub-group (4 oc each)
    const int pg  = tid >> 2;             // 0..31 pixel group
    const int pr  = pg >> 1;              // output row in tile 0..15
    const int pc0 = (pg & 1) * 16;        // output col base in tile

    float acc[4][16];
    #pragma unroll
    for (int i = 0; i < 4; i++)
        #pragma unroll
        for (int p = 0; p < 16; p++) acc[i][p] = 0.f;

    for (int ch = 0; ch < 8; ch++) {
        const int cc0 = ch * 8;

        // load input tile chunk: 8 channels x 18 rows x 34 cols (zero pad)
        for (int i = tid; i < 8 * 18 * 34; i += 128) {
            const int cc  = i / 612;
            const int rem = i - cc * 612;
            const int ri  = rem / 34;
            const int ci  = rem - ri * 34;
            const int gr  = r0 - 1 + ri;
            const int gc  = c0 - 1 + ci;
            float v = 0.f;
            if ((unsigned)gr < 128u && (unsigned)gc < 128u)
                v = x[(((size_t)b * CIN + cc0 + cc) * HH + gr) * WW + gc];
            sin_[cc][ri][ci] = v;
        }
        // load weight chunk: 8 c x 9 kk x 16 oc
        for (int j = tid; j < 1152; j += 128) {
            const int cc = j / 144;
            const int r2 = j - cc * 144;
            sw[j] = g_W2[(((size_t)b * CIN + cc0 + cc) * KK9 + (r2 >> 4)) * COUT
                         + ocg * 16 + (r2 & 15)];
        }
        __syncthreads();

        #pragma unroll 2
        for (int cc = 0; cc < 8; cc++) {
            #pragma unroll
            for (int kh = 0; kh < 3; kh++) {
                float in[18];
                const float4* rp = (const float4*)&sin_[cc][pr + kh][pc0];
                *(float4*)&in[0]  = rp[0];
                *(float4*)&in[4]  = rp[1];
                *(float4*)&in[8]  = rp[2];
                *(float4*)&in[12] = rp[3];
                in[16] = sin_[cc][pr + kh][pc0 + 16];
                in[17] = sin_[cc][pr + kh][pc0 + 17];
                #pragma unroll
                for (int kw = 0; kw < 3; kw++) {
                    const float4 w = *(const float4*)&sw[(cc * 9 + kh * 3 + kw) * 16 + og * 4];
                    #pragma unroll
                    for (int p = 0; p < 16; p++) {
                        const float xv = in[p + kw];
                        acc[0][p] = fmaf(w.x, xv, acc[0][p]);
                        acc[1][p] = fmaf(w.y, xv, acc[1][p]);
                        acc[2][p] = fmaf(w.z, xv, acc[2][p]);
                        acc[3][p] = fmaf(w.w, xv, acc[3][p]);
                    }
                }
            }
        }
        __syncthreads();
    }

    // epilogue: +bias, ReLU, vectorized stores
    #pragma unroll
    for (int i = 0; i < 4; i++) {
        const int oc = ocg * 16 + og * 4 + i;
        const float bv = bias[oc];
        float* op = out + ((((size_t)b * COUT + oc) * HH + (r0 + pr)) * WW + (c0 + pc0));
        #pragma unroll
        for (int q = 0; q < 4; q++) {
            float4 vv;
            vv.x = fmaxf(acc[i][q * 4 + 0] + bv, 0.f);
            vv.y = fmaxf(acc[i][q * 4 + 1] + bv, 0.f);
            vv.z = fmaxf(acc[i][q * 4 + 2] + bv, 0.f);
            vv.w = fmaxf(acc[i][q * 4 + 3] + bv, 0.f);
            ((float4*)op)[q] = vv;
        }
    }
}

// ---------------------------------------------------------------------------
// Launch
// ---------------------------------------------------------------------------
extern "C" void kernel_launch(void* const* d_in, const int* in_sizes, int n_in,
                              void* d_out, int out_size) {
    const float* x       = (const float*)d_in[0];
    const float* ctx_w   = (const float*)d_in[1];
    const float* ctx_b   = (const float*)d_in[2];
    const float* kg_w    = (const float*)d_in[3];
    const float* kg_b    = (const float*)d_in[4];
    const float* gamma   = (const float*)d_in[5];
    const float* bias    = (const float*)d_in[6];
    const float* value_w = (const float*)d_in[7];
    float* out = (float*)d_out;

    k_mean<<<NB * CIN, 256>>>(x);
    k_ctx<<<1, 128>>>(ctx_w, ctx_b);
    k_gen<<<NB * COUT, 576>>>(kg_w, kg_b, gamma, value_w);

    dim3 grid(4, 8, NB * 4);
    k_conv<<<grid, 128>>>(x, bias, out);
}